// round 11
// baseline (speedup 1.0000x reference)
#include <cuda_runtime.h>
#include <cuda_bf16.h>

// Problem constants
#define T_ 64
#define S_ 32
#define F_ 256
#define A_ 64
#define P2_ 64   // 2*P
#define NQ_ 2048 // T*S

// Scratch (device globals; no allocations allowed)
__device__ float g_theta[NQ_ * A_];
__device__ float g_xphi[NQ_ * A_];
__device__ float g_xg[NQ_ * F_];
__device__ float g_thetaB[NQ_ * P2_];
__device__ float g_thetaD[NQ_ * 16];      // 10 used, padded
__device__ float g_pos[S_ * S_ * P2_];    // pos[sigma][k][p]
__device__ float g_ctxg[NQ_ * F_];        // spatial ctx_g
__device__ float g_ctxp[NQ_ * P2_];       // temporal: btmp + cd@Wtmp
__device__ float g_ctxp2[NQ_ * P2_];      // spatial ctx_p (separate: no race)
// g_A4[sigma][t][tau] : temporal attention matrix (K-major operand for k4b)
__device__ float g_A4[S_ * T_ * T_];

// ---------------------------------------------------------------------------
// L1: seg 0..5 = projection GEMM x @ [Wa | WbX | WgX] (+thetaB/thetaD on seg0)
//     seg 6    = pos embedding (independent work, same launch)
// grid (64, 7), 256 threads. 32-row M tiles for occupancy (~3 CTAs/SM).
// ---------------------------------------------------------------------------
__global__ __launch_bounds__(256)
void k1_proj(const float* __restrict__ x,
             const float* __restrict__ Wa,
             const float* __restrict__ Wb,
             const float* __restrict__ Wg,
             const float* __restrict__ ba,
             const float* __restrict__ Wtmp,
             const float* __restrict__ positions,
             const float* __restrict__ Wpos,
             const float* __restrict__ bpos) {
    __shared__ float Xs[32][65];
    __shared__ float Ws[64 * 68];
    const int tid = threadIdx.x;
    const int m0 = blockIdx.x * 32;
    const int seg = blockIdx.y;

    if (seg == 6) {
        int base = blockIdx.x * 1024;
        #pragma unroll
        for (int li = 0; li < 4; li++) {
            int idx = base + tid + li * 256;
            int p = idx & 63;
            int jk = idx >> 6;
            int half = p >> 5, pp = p & 31;
            const float* src = positions + half * (S_*S_*9) + jk * 9;
            float s = bpos[pp];
            #pragma unroll
            for (int d = 0; d < 9; d++) s += src[d] * Wpos[d * 32 + pp];
            g_pos[idx] = s;
        }
        return;
    }

    const float* W;
    float* out;
    int ldw, coloff, ldo;
    bool addb = false;
    if (seg == 0)      { W = Wa; ldw = 64;  coloff = 0;          out = g_theta; ldo = 64;  addb = true; }
    else if (seg == 1) { W = Wb; ldw = 64;  coloff = 0;          out = g_xphi;  ldo = 64; }
    else               { W = Wg; ldw = 256; coloff = (seg-2)*64; out = g_xg;    ldo = 256; }

    const int tcol = tid & 15, trow = tid >> 4;   // trow 0..15 -> 2 rows each
    float acc[2][4] = {};

    for (int kk = 0; kk < 256; kk += 64) {
        #pragma unroll
        for (int li = 0; li < 2; li++) {
            int e = tid + li * 256;
            int r = e >> 4, c4 = (e & 15) << 2;
            float4 v = *reinterpret_cast<const float4*>(x + (m0 + r) * 256 + kk + c4);
            Xs[r][c4+0] = v.x; Xs[r][c4+1] = v.y; Xs[r][c4+2] = v.z; Xs[r][c4+3] = v.w;
        }
        #pragma unroll
        for (int li = 0; li < 4; li++) {
            int e = tid + li * 256;
            int r = e >> 4, c4 = (e & 15) << 2;
            float4 v = *reinterpret_cast<const float4*>(W + (kk + r) * ldw + coloff + c4);
            *reinterpret_cast<float4*>(&Ws[r * 68 + c4]) = v;
        }
        __syncthreads();
        #pragma unroll 16
        for (int k = 0; k < 64; k++) {
            float a[2];
            #pragma unroll
            for (int i = 0; i < 2; i++) a[i] = Xs[trow*2 + i][k];
            float4 bv = *reinterpret_cast<const float4*>(&Ws[k * 68 + tcol*4]);
            float b[4] = {bv.x, bv.y, bv.z, bv.w};
            #pragma unroll
            for (int i = 0; i < 2; i++)
                #pragma unroll
                for (int j = 0; j < 4; j++) acc[i][j] += a[i] * b[j];
        }
        __syncthreads();
    }
    #pragma unroll
    for (int i = 0; i < 2; i++) {
        int r = trow*2 + i;
        #pragma unroll
        for (int j = 0; j < 4; j++) {
            int c = tcol*4 + j;
            float v = acc[i][j];
            if (addb) v += ba[c];
            out[(m0 + r) * ldo + coloff + c] = v;
            if (seg == 0) Xs[r][c] = v;
        }
    }
    if (seg != 0) return;

    // --- thetaB = theta @ WbP^T : WbP laid out as Ws[a][p] ---
    __syncthreads();
    #pragma unroll
    for (int li = 0; li < 16; li++) {
        int e = tid + li * 256;            // e = p*64 + a
        int p = e >> 6, a = e & 63;
        Ws[a * 68 + p] = Wb[(256 + p) * 64 + a];
    }
    __syncthreads();
    float acc2[2][4] = {};
    #pragma unroll 16
    for (int a = 0; a < 64; a++) {
        float av[2];
        #pragma unroll
        for (int i = 0; i < 2; i++) av[i] = Xs[trow*2 + i][a];
        float4 bv = *reinterpret_cast<const float4*>(&Ws[a * 68 + tcol*4]);
        float b[4] = {bv.x, bv.y, bv.z, bv.w};
        #pragma unroll
        for (int i = 0; i < 2; i++)
            #pragma unroll
            for (int j = 0; j < 4; j++) acc2[i][j] += av[i] * b[j];
    }
    __syncthreads();
    #pragma unroll
    for (int i = 0; i < 2; i++) {
        int r = trow*2 + i;
        #pragma unroll
        for (int j = 0; j < 4; j++) {
            int p = tcol*4 + j;
            g_thetaB[(m0 + r) * 64 + p] = acc2[i][j];
            Xs[r][p] = acc2[i][j];
        }
    }
    __syncthreads();
    for (int e = tid; e < 320; e += 256) {
        int r = e / 10, d = e % 10;
        float s = 0.f;
        #pragma unroll
        for (int p = 0; p < 64; p++) s += Xs[r][p] * Wtmp[d * 64 + p];
        g_thetaD[(m0 + r) * 16 + d] = s;
    }
}

// ---------------------------------------------------------------------------
// L2: kbig. blocks 0..511 = temporal scores (writes g_A4, g_ctxp);
//          blocks 512..767 = spatial attention with inline posscore
//          (writes g_ctxg, g_ctxp2). Both depend only on L1.
// ---------------------------------------------------------------------------
__global__ __launch_bounds__(256)
void kbig(const float* __restrict__ temp,
          const float* __restrict__ Wtmp,
          const float* __restrict__ btmp) {
    __shared__ float sm[11560];
    int tid = threadIdx.x, lane = tid & 31, w = tid >> 5;

    if (blockIdx.x < 512) {
        // ---- temporal branch ----
        float* xphi = sm;            // 64*65 = 4160
        float* Th   = sm + 4160;     // 4*64
        float* Td   = sm + 4416;     // 4*16
        float* bsh  = sm + 4480;     // 64*4
        float* cdp  = sm + 4736;     // 8*10
        float* cdc  = sm + 4816;     // 4*10
        float* mxs  = sm + 4856;     // 8
        float* sms  = sm + 4864;     // 8

        int b2 = blockIdx.x;
        int sigma = b2 & 31;
        int tg = b2 >> 5;                  // 0..15, taus [tg*4, tg*4+4)
        int tl = w & 3, h2 = w >> 2;
        int tau = tg * 4 + tl;
        int t = lane + 32 * h2;

        for (int e = tid; e < 1024; e += 256) {
            int r = e >> 4, c4 = (e & 15) << 2;
            float4 v = *reinterpret_cast<const float4*>(g_xphi + (r * 32 + sigma) * 64 + c4);
            xphi[r * 65 + c4 + 0] = v.x; xphi[r * 65 + c4 + 1] = v.y;
            xphi[r * 65 + c4 + 2] = v.z; xphi[r * 65 + c4 + 3] = v.w;
        }
        Th[tid] = g_theta[((tg * 4 + (tid >> 6)) * 32 + sigma) * 64 + (tid & 63)];
        if (tid < 64)
            Td[tid] = g_thetaD[((tg * 4 + (tid >> 4)) * 32 + sigma) * 16 + (tid & 15)];

        float tp[10];
        {
            const float2* src = reinterpret_cast<const float2*>(
                temp + (((tau * 64 + t) * 32) + sigma) * 10);
            #pragma unroll
            for (int i = 0; i < 5; i++) { float2 v = src[i]; tp[2*i] = v.x; tp[2*i+1] = v.y; }
        }
        __syncthreads();

        float s = 0.f;
        #pragma unroll
        for (int a = 0; a < 64; a++) s += Th[tl * 64 + a] * xphi[t * 65 + a];
        #pragma unroll
        for (int d = 0; d < 10; d++) s += Td[tl * 16 + d] * tp[d];

        float m = s;
        #pragma unroll
        for (int o = 16; o; o >>= 1) m = fmaxf(m, __shfl_xor_sync(0xffffffffu, m, o));
        if (lane == 0) mxs[w] = m;
        __syncthreads();
        float M = fmaxf(mxs[tl], mxs[tl + 4]);
        float e = __expf(s - M);
        float psum = e;
        #pragma unroll
        for (int o = 16; o; o >>= 1) psum += __shfl_xor_sync(0xffffffffu, psum, o);
        if (lane == 0) sms[w] = psum;
        __syncthreads();
        float b = e / (sms[tl] + sms[tl + 4]);
        bsh[t * 4 + tl] = b;

        #pragma unroll
        for (int d = 0; d < 10; d++) {
            float v = b * tp[d];
            #pragma unroll
            for (int o = 16; o; o >>= 1) v += __shfl_xor_sync(0xffffffffu, v, o);
            if (lane == d) cdp[w * 10 + d] = v;
        }
        __syncthreads();
        if (tid < 40) cdc[tid] = cdp[tid] + cdp[tid + 40];
        __syncthreads();

        {
            int tl2 = tid >> 6, p = tid & 63;
            int q = (tg * 4 + tl2) * 32 + sigma;
            float v = btmp[p];
            #pragma unroll
            for (int d = 0; d < 10; d++) v += cdc[tl2 * 10 + d] * Wtmp[d * 64 + p];
            g_ctxp[q * 64 + p] = v;
        }

        __syncthreads();
        float* A = g_A4 + sigma * (64 * 64) + tg * 4;
        if (tid < 64) {
            *reinterpret_cast<float4*>(A + tid * 64) =
                *reinterpret_cast<const float4*>(bsh + tid * 4);
        }
        return;
    }

    // ---- spatial branch (inline posscore) ----
    float* xphi_s = sm;           // 32*65 = 2080
    float* xg_s   = sm + 2080;    // 32*256 = 8192
    float* Th     = sm + 10272;   // 8*64
    float* TB     = sm + 10784;   // 8*64
    float* asc    = sm + 11296;   // 8*33

    int b3 = blockIdx.x - 512;
    int tau = b3 >> 2;
    int sq = b3 & 3;              // sigmas [sq*8, sq*8+8)

    for (int e = tid; e < 512; e += 256) {
        int k = e >> 4, c4 = (e & 15) << 2;
        float4 v = *reinterpret_cast<const float4*>(g_xphi + (tau * 32 + k) * 64 + c4);
        xphi_s[k * 65 + c4 + 0] = v.x; xphi_s[k * 65 + c4 + 1] = v.y;
        xphi_s[k * 65 + c4 + 2] = v.z; xphi_s[k * 65 + c4 + 3] = v.w;
    }
    for (int e = tid; e < 2048; e += 256) {
        int k = e >> 6, c4 = (e & 63) << 2;
        float4 v = *reinterpret_cast<const float4*>(g_xg + (tau * 32 + k) * 256 + c4);
        *reinterpret_cast<float4*>(&xg_s[k * 256 + c4]) = v;
    }
    for (int e = tid; e < 512; e += 256) {
        int sig = e >> 6, c = e & 63;
        Th[sig * 64 + c] = g_theta[(tau * 32 + sq * 8 + sig) * 64 + c];
        TB[sig * 64 + c] = g_thetaB[(tau * 32 + sq * 8 + sig) * 64 + c];
    }
    __syncthreads();

    // scores (incl. inline posscore): warp w = sigma sq*8+w, lane = k
    {
        int sigma = sq * 8 + w;
        float s = 0.f;
        #pragma unroll
        for (int a = 0; a < 64; a++) s += Th[w * 64 + a] * xphi_s[lane * 65 + a];
        const float4* pp = reinterpret_cast<const float4*>(
            g_pos + sigma * 2048 + lane * 64);
        #pragma unroll
        for (int pg = 0; pg < 16; pg++) {
            float4 pv = pp[pg];
            s += TB[w * 64 + pg * 4 + 0] * pv.x + TB[w * 64 + pg * 4 + 1] * pv.y
               + TB[w * 64 + pg * 4 + 2] * pv.z + TB[w * 64 + pg * 4 + 3] * pv.w;
        }
        asc[w * 33 + lane] = s;
    }
    __syncwarp();

    // softmax (warp-local)
    {
        float s = asc[w * 33 + lane];
        float m = s;
        #pragma unroll
        for (int o = 16; o; o >>= 1) m = fmaxf(m, __shfl_xor_sync(0xffffffffu, m, o));
        float e = __expf(s - m);
        float sum = e;
        #pragma unroll
        for (int o = 16; o; o >>= 1) sum += __shfl_xor_sync(0xffffffffu, sum, o);
        asc[w * 33 + lane] = e / sum;
    }
    __syncwarp();

    // ctx: warp w owns sigma; lane covers 8 f's and 2 p's
    {
        int sigma = sq * 8 + w;
        int q = tau * 32 + sigma;
        float4 acc0 = {0,0,0,0}, acc1 = {0,0,0,0};
        float cp0 = 0.f, cp1 = 0.f;
        const float* posb = g_pos + sigma * (32 * 64);
        #pragma unroll 4
        for (int k = 0; k < 32; k++) {
            float aw = asc[w * 33 + k];
            const float* xr = &xg_s[k * 256 + lane * 8];
            float4 x0 = *reinterpret_cast<const float4*>(xr + 0);
            float4 x1 = *reinterpret_cast<const float4*>(xr + 4);
            acc0.x += aw*x0.x; acc0.y += aw*x0.y; acc0.z += aw*x0.z; acc0.w += aw*x0.w;
            acc1.x += aw*x1.x; acc1.y += aw*x1.y; acc1.z += aw*x1.z; acc1.w += aw*x1.w;
            float2 pv = *reinterpret_cast<const float2*>(posb + k * 64 + lane * 2);
            cp0 += aw * pv.x; cp1 += aw * pv.y;
        }
        float* og = g_ctxg + q * 256 + lane * 8;
        *reinterpret_cast<float4*>(og + 0) = acc0;
        *reinterpret_cast<float4*>(og + 4) = acc1;
        float2 cpv; cpv.x = cp0; cpv.y = cp1;
        *reinterpret_cast<float2*>(g_ctxp2 + q * 64 + lane * 2) = cpv;
    }
}

// ---------------------------------------------------------------------------
// L3: out[tau,f] = [attn | ctxp+ctxp2]^T(64x128) @ [xg ; WgP](128x64)
//                  + ctxg + 2bg.
// grid 256 = (sigma 32, fc 4, tau-half 2); tile 32tau x 64f, 2x4 micro.
// ---------------------------------------------------------------------------
__global__ __launch_bounds__(256)
void k4b_out(const float* __restrict__ Wg,
             const float* __restrict__ bg,
             float* __restrict__ out) {
    __shared__ float As[64 * 36];   // [k][tau32], stride 36
    __shared__ float Bs[64 * 64];   // [k][f]
    int tid = threadIdx.x;
    int b = blockIdx.x;
    int sigma = b & 31;
    int fc = (b >> 5) & 3;
    int th = b >> 7;                // tau half: taus [th*32, th*32+32)
    int f0 = fc * 64;

    const int tcol = tid & 15, trow = tid >> 4;   // trow: 16 -> 2 taus each
    float acc[2][4] = {};

    #pragma unroll
    for (int kc = 0; kc < 2; kc++) {
        if (kc == 0) {
            const float* Ag = g_A4 + sigma * (64 * 64) + th * 32;
            for (int e = tid; e < 512; e += 256) {
                int k = e >> 3, c4 = (e & 7) << 2;
                float4 v = *reinterpret_cast<const float4*>(Ag + k * 64 + c4);
                *reinterpret_cast<float4*>(&As[k * 36 + c4]) = v;
            }
            for (int e = tid; e < 1024; e += 256) {
                int r = e >> 4, c4 = (e & 15) << 2;
                float4 v = *reinterpret_cast<const float4*>(
                    g_xg + (r * 32 + sigma) * 256 + f0 + c4);
                *reinterpret_cast<float4*>(&Bs[r * 64 + c4]) = v;
            }
        } else {
            // A = transpose of (g_ctxp + g_ctxp2) tile (32 tau x 64 p)
            for (int e = tid; e < 512; e += 256) {
                int tl = e >> 4, pg = e & 15;
                int q = (th * 32 + tl) * 32 + sigma;
                float4 v = *reinterpret_cast<const float4*>(g_ctxp + q * 64 + pg * 4);
                float4 u = *reinterpret_cast<const float4*>(g_ctxp2 + q * 64 + pg * 4);
                As[(pg * 4 + 0) * 36 + tl] = v.x + u.x;
                As[(pg * 4 + 1) * 36 + tl] = v.y + u.y;
                As[(pg * 4 + 2) * 36 + tl] = v.z + u.z;
                As[(pg * 4 + 3) * 36 + tl] = v.w + u.w;
            }
            for (int e = tid; e < 1024; e += 256) {
                int r = e >> 4, c4 = (e & 15) << 2;
                float4 v = *reinterpret_cast<const float4*>(
                    Wg + (256 + r) * 256 + f0 + c4);
                *reinterpret_cast<float4*>(&Bs[r * 64 + c4]) = v;
            }
        }
        __syncthreads();
        #pragma unroll 8
        for (int k = 0; k < 64; k++) {
            float2 av = *reinterpret_cast<const float2*>(&As[k * 36 + trow * 2]);
            float4 bv = *reinterpret_cast<const float4*>(&Bs[k * 64 + tcol * 4]);
            acc[0][0] += av.x * bv.x; acc[0][1] += av.x * bv.y;
            acc[0][2] += av.x * bv.z; acc[0][3] += av.x * bv.w;
            acc[1][0] += av.y * bv.x; acc[1][1] += av.y * bv.y;
            acc[1][2] += av.y * bv.z; acc[1][3] += av.y * bv.w;
        }
        __syncthreads();
    }

    float4 bgv = *reinterpret_cast<const float4*>(bg + f0 + tcol * 4);
    #pragma unroll
    for (int i = 0; i < 2; i++) {
        int tau = th * 32 + trow * 2 + i;
        int o = (tau * 32 + sigma) * 256 + f0 + tcol * 4;
        float4 cg = *reinterpret_cast<const float4*>(g_ctxg + o);
        float4 r;
        r.x = acc[i][0] + cg.x + 2.f * bgv.x;
        r.y = acc[i][1] + cg.y + 2.f * bgv.y;
        r.z = acc[i][2] + cg.z + 2.f * bgv.z;
        r.w = acc[i][3] + cg.w + 2.f * bgv.w;
        *reinterpret_cast<float4*>(out + o) = r;
    }
}

// ---------------------------------------------------------------------------
extern "C" void kernel_launch(void* const* d_in, const int* in_sizes, int n_in,
                              void* d_out, int out_size) {
    (void)in_sizes; (void)n_in; (void)out_size;
    const float* batch_data = (const float*)d_in[0];
    const float* positions  = (const float*)d_in[1];
    const float* temp       = (const float*)d_in[2];
    const float* Wa         = (const float*)d_in[3];
    const float* ba         = (const float*)d_in[4];
    const float* Wb         = (const float*)d_in[5];
    // d_in[6] = bb : cancels in softmax -> unused
    const float* Wg         = (const float*)d_in[7];
    const float* bg         = (const float*)d_in[8];
    const float* Wpos       = (const float*)d_in[9];
    const float* bpos       = (const float*)d_in[10];
    const float* Wtmp       = (const float*)d_in[11];
    const float* btmp       = (const float*)d_in[12];
    float* out = (float*)d_out;

    k1_proj<<<dim3(64, 7), 256>>>(batch_data, Wa, Wb, Wg, ba, Wtmp,
                                  positions, Wpos, bpos);
    kbig<<<768, 256>>>(temp, Wtmp, btmp);
    k4b_out<<<256, 256>>>(Wg, bg, out);
}

// round 12
// speedup vs baseline: 1.0285x; 1.0285x over previous
#include <cuda_runtime.h>
#include <cuda_bf16.h>

// Problem constants
#define T_ 64
#define S_ 32
#define F_ 256
#define A_ 64
#define P2_ 64   // 2*P
#define NQ_ 2048 // T*S

// Scratch (device globals; no allocations allowed)
__device__ float g_theta[NQ_ * A_];
__device__ float g_xphi[NQ_ * A_];
__device__ float g_xg[NQ_ * F_];
__device__ float g_thetaB[NQ_ * P2_];
__device__ float g_thetaD[NQ_ * 16];      // 10 used, padded
__device__ float g_pos[S_ * S_ * P2_];    // pos[sigma][k][p]
__device__ float g_ctxg[NQ_ * F_];        // spatial ctx_g
__device__ float g_ctxp[NQ_ * P2_];       // temporal: btmp + cd@Wtmp
__device__ float g_ctxp2[NQ_ * P2_];      // spatial ctx_p (separate: no race)
// g_A4[sigma][t][tau] : temporal attention matrix (K-major operand for k4b)
__device__ float g_A4[S_ * T_ * T_];

// k1 dynamic smem: 2 X buffers (64x65) + 2 W buffers (64x68)
#define K1_XBUF 4160
#define K1_WBUF 4352
#define K1_SMEMF (2 * K1_XBUF + 2 * K1_WBUF)   // 17024 floats
#define K1_SMEMB (K1_SMEMF * 4)                // 68096 bytes

// ---------------------------------------------------------------------------
// L1: seg 0..5 = projection GEMM x @ [Wa | WbX | WgX] (+thetaB/thetaD on seg0)
//     seg 6    = pos embedding (independent work, same launch)
// grid (32, 7), 256 threads, 64-row M tiles, 4x4 micro-tile,
// double-buffered smem software pipeline (1 barrier per K chunk).
// ---------------------------------------------------------------------------
__global__ __launch_bounds__(256)
void k1_proj(const float* __restrict__ x,
             const float* __restrict__ Wa,
             const float* __restrict__ Wb,
             const float* __restrict__ Wg,
             const float* __restrict__ ba,
             const float* __restrict__ Wtmp,
             const float* __restrict__ positions,
             const float* __restrict__ Wpos,
             const float* __restrict__ bpos) {
    extern __shared__ float dsm[];
    const int tid = threadIdx.x;
    const int m0 = blockIdx.x * 64;
    const int seg = blockIdx.y;

    if (seg == 6) {
        int base = blockIdx.x * 2048;
        #pragma unroll
        for (int li = 0; li < 8; li++) {
            int idx = base + tid + li * 256;
            int p = idx & 63;
            int jk = idx >> 6;
            int half = p >> 5, pp = p & 31;
            const float* src = positions + half * (S_*S_*9) + jk * 9;
            float s = bpos[pp];
            #pragma unroll
            for (int d = 0; d < 9; d++) s += src[d] * Wpos[d * 32 + pp];
            g_pos[idx] = s;
        }
        return;
    }

    float* Xb0 = dsm;
    float* Xb1 = dsm + K1_XBUF;
    float* Wb0 = dsm + 2 * K1_XBUF;
    float* Wb1 = dsm + 2 * K1_XBUF + K1_WBUF;

    const float* W;
    float* out;
    int ldw, coloff, ldo;
    bool addb = false;
    if (seg == 0)      { W = Wa; ldw = 64;  coloff = 0;          out = g_theta; ldo = 64;  addb = true; }
    else if (seg == 1) { W = Wb; ldw = 64;  coloff = 0;          out = g_xphi;  ldo = 64; }
    else               { W = Wg; ldw = 256; coloff = (seg-2)*64; out = g_xg;    ldo = 256; }

    const int tcol = tid & 15, trow = tid >> 4;
    float acc[4][4] = {};

    // per-thread (r, c4) for staging
    const int sr = tid >> 4;                 // with e = tid + li*256: r = sr + li*16
    const int sc4 = (tid & 15) << 2;

    float4 xr[4], wr[4];
    // prefetch chunk 0
    #pragma unroll
    for (int li = 0; li < 4; li++) {
        int r = sr + li * 16;
        xr[li] = *reinterpret_cast<const float4*>(x + (m0 + r) * 256 + sc4);
        wr[li] = *reinterpret_cast<const float4*>(W + r * ldw + coloff + sc4);
    }

    #pragma unroll
    for (int kc = 0; kc < 4; kc++) {
        float* Xs = (kc & 1) ? Xb1 : Xb0;
        float* Ws = (kc & 1) ? Wb1 : Wb0;
        // stage current chunk (Xs stride 65: scalar; Ws stride 68: float4)
        #pragma unroll
        for (int li = 0; li < 4; li++) {
            int r = sr + li * 16;
            Xs[r * 65 + sc4 + 0] = xr[li].x; Xs[r * 65 + sc4 + 1] = xr[li].y;
            Xs[r * 65 + sc4 + 2] = xr[li].z; Xs[r * 65 + sc4 + 3] = xr[li].w;
            *reinterpret_cast<float4*>(&Ws[r * 68 + sc4]) = wr[li];
        }
        __syncthreads();
        // prefetch next chunk (overlaps with compute below)
        if (kc < 3) {
            int kk = (kc + 1) * 64;
            #pragma unroll
            for (int li = 0; li < 4; li++) {
                int r = sr + li * 16;
                xr[li] = *reinterpret_cast<const float4*>(x + (m0 + r) * 256 + kk + sc4);
                wr[li] = *reinterpret_cast<const float4*>(W + (kk + r) * ldw + coloff + sc4);
            }
        }
        #pragma unroll 16
        for (int k = 0; k < 64; k++) {
            float a[4];
            #pragma unroll
            for (int i = 0; i < 4; i++) a[i] = Xs[(trow*4 + i) * 65 + k];
            float4 bv = *reinterpret_cast<const float4*>(&Ws[k * 68 + tcol*4]);
            float b[4] = {bv.x, bv.y, bv.z, bv.w};
            #pragma unroll
            for (int i = 0; i < 4; i++)
                #pragma unroll
                for (int j = 0; j < 4; j++) acc[i][j] += a[i] * b[j];
        }
        if (kc < 3) __syncthreads();
    }

    #pragma unroll
    for (int i = 0; i < 4; i++) {
        int r = trow*4 + i;
        #pragma unroll
        for (int j = 0; j < 4; j++) {
            int c = tcol*4 + j;
            float v = acc[i][j];
            if (addb) v += ba[c];
            out[(m0 + r) * ldo + coloff + c] = v;
            if (seg == 0) Xb0[r * 65 + c] = v;   // keep theta for thetaB stage
        }
    }
    if (seg != 0) return;

    // --- thetaB = theta @ WbP^T : WbP laid out as Wb0[a][p] ---
    __syncthreads();
    #pragma unroll
    for (int li = 0; li < 16; li++) {
        int e = tid + li * 256;            // e = p*64 + a
        int p = e >> 6, a = e & 63;
        Wb0[a * 68 + p] = Wb[(256 + p) * 64 + a];
    }
    __syncthreads();
    float acc2[4][4] = {};
    #pragma unroll 16
    for (int a = 0; a < 64; a++) {
        float av[4];
        #pragma unroll
        for (int i = 0; i < 4; i++) av[i] = Xb0[(trow*4 + i) * 65 + a];
        float4 bv = *reinterpret_cast<const float4*>(&Wb0[a * 68 + tcol*4]);
        float b[4] = {bv.x, bv.y, bv.z, bv.w};
        #pragma unroll
        for (int i = 0; i < 4; i++)
            #pragma unroll
            for (int j = 0; j < 4; j++) acc2[i][j] += av[i] * b[j];
    }
    __syncthreads();
    #pragma unroll
    for (int i = 0; i < 4; i++) {
        int r = trow*4 + i;
        #pragma unroll
        for (int j = 0; j < 4; j++) {
            int p = tcol*4 + j;
            g_thetaB[(m0 + r) * 64 + p] = acc2[i][j];
            Xb0[r * 65 + p] = acc2[i][j];
        }
    }
    __syncthreads();
    for (int e = tid; e < 640; e += 256) {
        int r = e / 10, d = e % 10;
        float s = 0.f;
        #pragma unroll
        for (int p = 0; p < 64; p++) s += Xb0[r * 65 + p] * Wtmp[d * 64 + p];
        g_thetaD[(m0 + r) * 16 + d] = s;
    }
}

// ---------------------------------------------------------------------------
// L2: kbig. blocks 0..511 = temporal scores (writes g_A4, g_ctxp);
//          blocks 512..767 = spatial attention with inline posscore
//          (writes g_ctxg, g_ctxp2). Both depend only on L1.
// ---------------------------------------------------------------------------
__global__ __launch_bounds__(256)
void kbig(const float* __restrict__ temp,
          const float* __restrict__ Wtmp,
          const float* __restrict__ btmp) {
    __shared__ float sm[11560];
    int tid = threadIdx.x, lane = tid & 31, w = tid >> 5;

    if (blockIdx.x < 512) {
        // ---- temporal branch ----
        float* xphi = sm;            // 64*65 = 4160
        float* Th   = sm + 4160;     // 4*64
        float* Td   = sm + 4416;     // 4*16
        float* bsh  = sm + 4480;     // 64*4
        float* cdp  = sm + 4736;     // 8*10
        float* cdc  = sm + 4816;     // 4*10
        float* mxs  = sm + 4856;     // 8
        float* sms  = sm + 4864;     // 8

        int b2 = blockIdx.x;
        int sigma = b2 & 31;
        int tg = b2 >> 5;                  // 0..15, taus [tg*4, tg*4+4)
        int tl = w & 3, h2 = w >> 2;
        int tau = tg * 4 + tl;
        int t = lane + 32 * h2;

        for (int e = tid; e < 1024; e += 256) {
            int r = e >> 4, c4 = (e & 15) << 2;
            float4 v = *reinterpret_cast<const float4*>(g_xphi + (r * 32 + sigma) * 64 + c4);
            xphi[r * 65 + c4 + 0] = v.x; xphi[r * 65 + c4 + 1] = v.y;
            xphi[r * 65 + c4 + 2] = v.z; xphi[r * 65 + c4 + 3] = v.w;
        }
        Th[tid] = g_theta[((tg * 4 + (tid >> 6)) * 32 + sigma) * 64 + (tid & 63)];
        if (tid < 64)
            Td[tid] = g_thetaD[((tg * 4 + (tid >> 4)) * 32 + sigma) * 16 + (tid & 15)];

        float tp[10];
        {
            const float2* src = reinterpret_cast<const float2*>(
                temp + (((tau * 64 + t) * 32) + sigma) * 10);
            #pragma unroll
            for (int i = 0; i < 5; i++) { float2 v = src[i]; tp[2*i] = v.x; tp[2*i+1] = v.y; }
        }
        __syncthreads();

        float s = 0.f;
        #pragma unroll
        for (int a = 0; a < 64; a++) s += Th[tl * 64 + a] * xphi[t * 65 + a];
        #pragma unroll
        for (int d = 0; d < 10; d++) s += Td[tl * 16 + d] * tp[d];

        float m = s;
        #pragma unroll
        for (int o = 16; o; o >>= 1) m = fmaxf(m, __shfl_xor_sync(0xffffffffu, m, o));
        if (lane == 0) mxs[w] = m;
        __syncthreads();
        float M = fmaxf(mxs[tl], mxs[tl + 4]);
        float e = __expf(s - M);
        float psum = e;
        #pragma unroll
        for (int o = 16; o; o >>= 1) psum += __shfl_xor_sync(0xffffffffu, psum, o);
        if (lane == 0) sms[w] = psum;
        __syncthreads();
        float b = e / (sms[tl] + sms[tl + 4]);
        bsh[t * 4 + tl] = b;

        #pragma unroll
        for (int d = 0; d < 10; d++) {
            float v = b * tp[d];
            #pragma unroll
            for (int o = 16; o; o >>= 1) v += __shfl_xor_sync(0xffffffffu, v, o);
            if (lane == d) cdp[w * 10 + d] = v;
        }
        __syncthreads();
        if (tid < 40) cdc[tid] = cdp[tid] + cdp[tid + 40];
        __syncthreads();

        {
            int tl2 = tid >> 6, p = tid & 63;
            int q = (tg * 4 + tl2) * 32 + sigma;
            float v = btmp[p];
            #pragma unroll
            for (int d = 0; d < 10; d++) v += cdc[tl2 * 10 + d] * Wtmp[d * 64 + p];
            g_ctxp[q * 64 + p] = v;
        }

        __syncthreads();
        float* A = g_A4 + sigma * (64 * 64) + tg * 4;
        if (tid < 64) {
            *reinterpret_cast<float4*>(A + tid * 64) =
                *reinterpret_cast<const float4*>(bsh + tid * 4);
        }
        return;
    }

    // ---- spatial branch (inline posscore) ----
    float* xphi_s = sm;           // 32*65 = 2080
    float* xg_s   = sm + 2080;    // 32*256 = 8192
    float* Th     = sm + 10272;   // 8*64
    float* TB     = sm + 10784;   // 8*64
    float* asc    = sm + 11296;   // 8*33

    int b3 = blockIdx.x - 512;
    int tau = b3 >> 2;
    int sq = b3 & 3;              // sigmas [sq*8, sq*8+8)

    for (int e = tid; e < 512; e += 256) {
        int k = e >> 4, c4 = (e & 15) << 2;
        float4 v = *reinterpret_cast<const float4*>(g_xphi + (tau * 32 + k) * 64 + c4);
        xphi_s[k * 65 + c4 + 0] = v.x; xphi_s[k * 65 + c4 + 1] = v.y;
        xphi_s[k * 65 + c4 + 2] = v.z; xphi_s[k * 65 + c4 + 3] = v.w;
    }
    for (int e = tid; e < 2048; e += 256) {
        int k = e >> 6, c4 = (e & 63) << 2;
        float4 v = *reinterpret_cast<const float4*>(g_xg + (tau * 32 + k) * 256 + c4);
        *reinterpret_cast<float4*>(&xg_s[k * 256 + c4]) = v;
    }
    for (int e = tid; e < 512; e += 256) {
        int sig = e >> 6, c = e & 63;
        Th[sig * 64 + c] = g_theta[(tau * 32 + sq * 8 + sig) * 64 + c];
        TB[sig * 64 + c] = g_thetaB[(tau * 32 + sq * 8 + sig) * 64 + c];
    }
    __syncthreads();

    // scores (incl. inline posscore): warp w = sigma sq*8+w, lane = k
    {
        int sigma = sq * 8 + w;
        float s = 0.f;
        #pragma unroll
        for (int a = 0; a < 64; a++) s += Th[w * 64 + a] * xphi_s[lane * 65 + a];
        const float4* pp = reinterpret_cast<const float4*>(
            g_pos + sigma * 2048 + lane * 64);
        #pragma unroll
        for (int pg = 0; pg < 16; pg++) {
            float4 pv = pp[pg];
            s += TB[w * 64 + pg * 4 + 0] * pv.x + TB[w * 64 + pg * 4 + 1] * pv.y
               + TB[w * 64 + pg * 4 + 2] * pv.z + TB[w * 64 + pg * 4 + 3] * pv.w;
        }
        asc[w * 33 + lane] = s;
    }
    __syncwarp();

    // softmax (warp-local)
    {
        float s = asc[w * 33 + lane];
        float m = s;
        #pragma unroll
        for (int o = 16; o; o >>= 1) m = fmaxf(m, __shfl_xor_sync(0xffffffffu, m, o));
        float e = __expf(s - m);
        float sum = e;
        #pragma unroll
        for (int o = 16; o; o >>= 1) sum += __shfl_xor_sync(0xffffffffu, sum, o);
        asc[w * 33 + lane] = e / sum;
    }
    __syncwarp();

    // ctx: warp w owns sigma; lane covers 8 f's and 2 p's
    {
        int sigma = sq * 8 + w;
        int q = tau * 32 + sigma;
        float4 acc0 = {0,0,0,0}, acc1 = {0,0,0,0};
        float cp0 = 0.f, cp1 = 0.f;
        const float* posb = g_pos + sigma * (32 * 64);
        #pragma unroll 4
        for (int k = 0; k < 32; k++) {
            float aw = asc[w * 33 + k];
            const float* xr = &xg_s[k * 256 + lane * 8];
            float4 x0 = *reinterpret_cast<const float4*>(xr + 0);
            float4 x1 = *reinterpret_cast<const float4*>(xr + 4);
            acc0.x += aw*x0.x; acc0.y += aw*x0.y; acc0.z += aw*x0.z; acc0.w += aw*x0.w;
            acc1.x += aw*x1.x; acc1.y += aw*x1.y; acc1.z += aw*x1.z; acc1.w += aw*x1.w;
            float2 pv = *reinterpret_cast<const float2*>(posb + k * 64 + lane * 2);
            cp0 += aw * pv.x; cp1 += aw * pv.y;
        }
        float* og = g_ctxg + q * 256 + lane * 8;
        *reinterpret_cast<float4*>(og + 0) = acc0;
        *reinterpret_cast<float4*>(og + 4) = acc1;
        float2 cpv; cpv.x = cp0; cpv.y = cp1;
        *reinterpret_cast<float2*>(g_ctxp2 + q * 64 + lane * 2) = cpv;
    }
}

// ---------------------------------------------------------------------------
// L3: out[tau,f] = [attn | ctxp+ctxp2]^T(64x128) @ [xg ; WgP](128x64)
//                  + ctxg + 2bg.
// grid 256 = (sigma 32, fc 4, tau-half 2); tile 32tau x 64f, 2x4 micro.
// ---------------------------------------------------------------------------
__global__ __launch_bounds__(256)
void k4b_out(const float* __restrict__ Wg,
             const float* __restrict__ bg,
             float* __restrict__ out) {
    __shared__ float As[64 * 36];   // [k][tau32], stride 36
    __shared__ float Bs[64 * 64];   // [k][f]
    int tid = threadIdx.x;
    int b = blockIdx.x;
    int sigma = b & 31;
    int fc = (b >> 5) & 3;
    int th = b >> 7;                // tau half: taus [th*32, th*32+32)
    int f0 = fc * 64;

    const int tcol = tid & 15, trow = tid >> 4;   // trow: 16 -> 2 taus each
    float acc[2][4] = {};

    #pragma unroll
    for (int kc = 0; kc < 2; kc++) {
        if (kc == 0) {
            const float* Ag = g_A4 + sigma * (64 * 64) + th * 32;
            for (int e = tid; e < 512; e += 256) {
                int k = e >> 3, c4 = (e & 7) << 2;
                float4 v = *reinterpret_cast<const float4*>(Ag + k * 64 + c4);
                *reinterpret_cast<float4*>(&As[k * 36 + c4]) = v;
            }
            for (int e = tid; e < 1024; e += 256) {
                int r = e >> 4, c4 = (e & 15) << 2;
                float4 v = *reinterpret_cast<const float4*>(
                    g_xg + (r * 32 + sigma) * 256 + f0 + c4);
                *reinterpret_cast<float4*>(&Bs[r * 64 + c4]) = v;
            }
        } else {
            // A = transpose of (g_ctxp + g_ctxp2) tile (32 tau x 64 p)
            for (int e = tid; e < 512; e += 256) {
                int tl = e >> 4, pg = e & 15;
                int q = (th * 32 + tl) * 32 + sigma;
                float4 v = *reinterpret_cast<const float4*>(g_ctxp + q * 64 + pg * 4);
                float4 u = *reinterpret_cast<const float4*>(g_ctxp2 + q * 64 + pg * 4);
                As[(pg * 4 + 0) * 36 + tl] = v.x + u.x;
                As[(pg * 4 + 1) * 36 + tl] = v.y + u.y;
                As[(pg * 4 + 2) * 36 + tl] = v.z + u.z;
                As[(pg * 4 + 3) * 36 + tl] = v.w + u.w;
            }
            for (int e = tid; e < 1024; e += 256) {
                int r = e >> 4, c4 = (e & 15) << 2;
                float4 v = *reinterpret_cast<const float4*>(
                    Wg + (256 + r) * 256 + f0 + c4);
                *reinterpret_cast<float4*>(&Bs[r * 64 + c4]) = v;
            }
        }
        __syncthreads();
        #pragma unroll 8
        for (int k = 0; k < 64; k++) {
            float2 av = *reinterpret_cast<const float2*>(&As[k * 36 + trow * 2]);
            float4 bv = *reinterpret_cast<const float4*>(&Bs[k * 64 + tcol * 4]);
            acc[0][0] += av.x * bv.x; acc[0][1] += av.x * bv.y;
            acc[0][2] += av.x * bv.z; acc[0][3] += av.x * bv.w;
            acc[1][0] += av.y * bv.x; acc[1][1] += av.y * bv.y;
            acc[1][2] += av.y * bv.z; acc[1][3] += av.y * bv.w;
        }
        __syncthreads();
    }

    float4 bgv = *reinterpret_cast<const float4*>(bg + f0 + tcol * 4);
    #pragma unroll
    for (int i = 0; i < 2; i++) {
        int tau = th * 32 + trow * 2 + i;
        int o = (tau * 32 + sigma) * 256 + f0 + tcol * 4;
        float4 cg = *reinterpret_cast<const float4*>(g_ctxg + o);
        float4 r;
        r.x = acc[i][0] + cg.x + 2.f * bgv.x;
        r.y = acc[i][1] + cg.y + 2.f * bgv.y;
        r.z = acc[i][2] + cg.z + 2.f * bgv.z;
        r.w = acc[i][3] + cg.w + 2.f * bgv.w;
        *reinterpret_cast<float4*>(out + o) = r;
    }
}

// ---------------------------------------------------------------------------
extern "C" void kernel_launch(void* const* d_in, const int* in_sizes, int n_in,
                              void* d_out, int out_size) {
    (void)in_sizes; (void)n_in; (void)out_size;
    const float* batch_data = (const float*)d_in[0];
    const float* positions  = (const float*)d_in[1];
    const float* temp       = (const float*)d_in[2];
    const float* Wa         = (const float*)d_in[3];
    const float* ba         = (const float*)d_in[4];
    const float* Wb         = (const float*)d_in[5];
    // d_in[6] = bb : cancels in softmax -> unused
    const float* Wg         = (const float*)d_in[7];
    const float* bg         = (const float*)d_in[8];
    const float* Wpos       = (const float*)d_in[9];
    const float* bpos       = (const float*)d_in[10];
    const float* Wtmp       = (const float*)d_in[11];
    const float* btmp       = (const float*)d_in[12];
    float* out = (float*)d_out;

    cudaFuncSetAttribute((const void*)k1_proj,
                         cudaFuncAttributeMaxDynamicSharedMemorySize, K1_SMEMB);

    k1_proj<<<dim3(32, 7), 256, K1_SMEMB>>>(batch_data, Wa, Wb, Wg, ba, Wtmp,
                                            positions, Wpos, bpos);
    kbig<<<768, 256>>>(temp, Wtmp, btmp);
    k4b_out<<<256, 256>>>(Wg, bg, out);
}

// round 13
// speedup vs baseline: 1.1381x; 1.1066x over previous
#include <cuda_runtime.h>
#include <cuda_bf16.h>

// Problem constants
#define T_ 64
#define S_ 32
#define F_ 256
#define A_ 64
#define P2_ 64   // 2*P
#define NQ_ 2048 // T*S

// Scratch (device globals; no allocations allowed)
__device__ float g_theta[NQ_ * A_];
__device__ float g_xphi[NQ_ * A_];
__device__ float g_xg[NQ_ * F_];
__device__ float g_thetaB[NQ_ * P2_];
__device__ float g_thetaD[NQ_ * 16];      // 10 used, padded
__device__ float g_pos[S_ * S_ * P2_];    // pos[sigma][k][p]
__device__ float g_ctxg[NQ_ * F_];        // spatial ctx_g
__device__ float g_ctxp[NQ_ * P2_];       // temporal: btmp + cd@Wtmp
__device__ float g_ctxp2[NQ_ * P2_];      // spatial ctx_p (separate: no race)
// g_A4[sigma][t][tau] : temporal attention matrix (K-major operand for k4b)
__device__ float g_A4[S_ * T_ * T_];

// ---------------------------------------------------------------------------
// L1: seg 0..5 = projection GEMM x @ [Wa | WbX | WgX] (+thetaB/thetaD on seg0)
//     seg 6    = pos embedding (independent work, same launch)
// grid (64, 7), 128 threads. 32M x 64N tiles, 4x4 micro-tile.
// 384 compute blocks -> single balanced wave (~6 blocks/SM).
// ---------------------------------------------------------------------------
__global__ __launch_bounds__(128)
void k1_proj(const float* __restrict__ x,
             const float* __restrict__ Wa,
             const float* __restrict__ Wb,
             const float* __restrict__ Wg,
             const float* __restrict__ ba,
             const float* __restrict__ Wtmp,
             const float* __restrict__ positions,
             const float* __restrict__ Wpos,
             const float* __restrict__ bpos) {
    __shared__ float Xs[32 * 65];
    __shared__ float Ws[64 * 68];
    const int tid = threadIdx.x;
    const int m0 = blockIdx.x * 32;
    const int seg = blockIdx.y;

    if (seg == 6) {
        int base = blockIdx.x * 1024;
        #pragma unroll
        for (int li = 0; li < 8; li++) {
            int idx = base + tid + li * 128;
            int p = idx & 63;
            int jk = idx >> 6;
            int half = p >> 5, pp = p & 31;
            const float* src = positions + half * (S_*S_*9) + jk * 9;
            float s = bpos[pp];
            #pragma unroll
            for (int d = 0; d < 9; d++) s += src[d] * Wpos[d * 32 + pp];
            g_pos[idx] = s;
        }
        return;
    }

    const float* W;
    float* out;
    int ldw, coloff, ldo;
    bool addb = false;
    if (seg == 0)      { W = Wa; ldw = 64;  coloff = 0;          out = g_theta; ldo = 64;  addb = true; }
    else if (seg == 1) { W = Wb; ldw = 64;  coloff = 0;          out = g_xphi;  ldo = 64; }
    else               { W = Wg; ldw = 256; coloff = (seg-2)*64; out = g_xg;    ldo = 256; }

    const int tcol = tid & 15, trow = tid >> 4;   // trow 0..7 -> 4 rows each
    float acc[4][4] = {};

    for (int kk = 0; kk < 256; kk += 64) {
        #pragma unroll
        for (int li = 0; li < 4; li++) {          // X: 32x64 = 512 float4
            int e = tid + li * 128;
            int r = e >> 4, c4 = (e & 15) << 2;
            float4 v = *reinterpret_cast<const float4*>(x + (m0 + r) * 256 + kk + c4);
            Xs[r * 65 + c4 + 0] = v.x; Xs[r * 65 + c4 + 1] = v.y;
            Xs[r * 65 + c4 + 2] = v.z; Xs[r * 65 + c4 + 3] = v.w;
        }
        #pragma unroll
        for (int li = 0; li < 8; li++) {          // W: 64x64 = 1024 float4
            int e = tid + li * 128;
            int r = e >> 4, c4 = (e & 15) << 2;
            float4 v = *reinterpret_cast<const float4*>(W + (kk + r) * ldw + coloff + c4);
            *reinterpret_cast<float4*>(&Ws[r * 68 + c4]) = v;
        }
        __syncthreads();
        #pragma unroll 16
        for (int k = 0; k < 64; k++) {
            float a[4];
            #pragma unroll
            for (int i = 0; i < 4; i++) a[i] = Xs[(trow*4 + i) * 65 + k];
            float4 bv = *reinterpret_cast<const float4*>(&Ws[k * 68 + tcol*4]);
            float b[4] = {bv.x, bv.y, bv.z, bv.w};
            #pragma unroll
            for (int i = 0; i < 4; i++)
                #pragma unroll
                for (int j = 0; j < 4; j++) acc[i][j] += a[i] * b[j];
        }
        __syncthreads();
    }
    #pragma unroll
    for (int i = 0; i < 4; i++) {
        int r = trow*4 + i;
        #pragma unroll
        for (int j = 0; j < 4; j++) {
            int c = tcol*4 + j;
            float v = acc[i][j];
            if (addb) v += ba[c];
            out[(m0 + r) * ldo + coloff + c] = v;
            if (seg == 0) Xs[r * 65 + c] = v;
        }
    }
    if (seg != 0) return;

    // --- thetaB = theta @ WbP^T : WbP laid out as Ws[a][p] ---
    __syncthreads();
    #pragma unroll
    for (int li = 0; li < 32; li++) {
        int e = tid + li * 128;            // e = p*64 + a
        int p = e >> 6, a = e & 63;
        Ws[a * 68 + p] = Wb[(256 + p) * 64 + a];
    }
    __syncthreads();
    float acc2[4][4] = {};
    #pragma unroll 16
    for (int a = 0; a < 64; a++) {
        float av[4];
        #pragma unroll
        for (int i = 0; i < 4; i++) av[i] = Xs[(trow*4 + i) * 65 + a];
        float4 bv = *reinterpret_cast<const float4*>(&Ws[a * 68 + tcol*4]);
        float b[4] = {bv.x, bv.y, bv.z, bv.w};
        #pragma unroll
        for (int i = 0; i < 4; i++)
            #pragma unroll
            for (int j = 0; j < 4; j++) acc2[i][j] += av[i] * b[j];
    }
    __syncthreads();
    #pragma unroll
    for (int i = 0; i < 4; i++) {
        int r = trow*4 + i;
        #pragma unroll
        for (int j = 0; j < 4; j++) {
            int p = tcol*4 + j;
            g_thetaB[(m0 + r) * 64 + p] = acc2[i][j];
            Xs[r * 65 + p] = acc2[i][j];
        }
    }
    __syncthreads();
    for (int e = tid; e < 320; e += 128) {
        int r = e / 10, d = e % 10;
        float s = 0.f;
        #pragma unroll
        for (int p = 0; p < 64; p++) s += Xs[r * 65 + p] * Wtmp[d * 64 + p];
        g_thetaD[(m0 + r) * 16 + d] = s;
    }
}

// ---------------------------------------------------------------------------
// L2: kbig. blocks 0..511 = temporal scores (writes g_A4, g_ctxp);
//          blocks 512..767 = spatial attention with inline posscore
//          (writes g_ctxg, g_ctxp2). Both depend only on L1.
// ---------------------------------------------------------------------------
__global__ __launch_bounds__(256)
void kbig(const float* __restrict__ temp,
          const float* __restrict__ Wtmp,
          const float* __restrict__ btmp) {
    __shared__ float sm[11560];
    int tid = threadIdx.x, lane = tid & 31, w = tid >> 5;

    if (blockIdx.x < 512) {
        // ---- temporal branch ----
        float* xphi = sm;            // 64*65 = 4160
        float* Th   = sm + 4160;     // 4*64
        float* Td   = sm + 4416;     // 4*16
        float* bsh  = sm + 4480;     // 64*4
        float* cdp  = sm + 4736;     // 8*10
        float* cdc  = sm + 4816;     // 4*10
        float* mxs  = sm + 4856;     // 8
        float* sms  = sm + 4864;     // 8

        int b2 = blockIdx.x;
        int sigma = b2 & 31;
        int tg = b2 >> 5;                  // 0..15, taus [tg*4, tg*4+4)
        int tl = w & 3, h2 = w >> 2;
        int tau = tg * 4 + tl;
        int t = lane + 32 * h2;

        for (int e = tid; e < 1024; e += 256) {
            int r = e >> 4, c4 = (e & 15) << 2;
            float4 v = *reinterpret_cast<const float4*>(g_xphi + (r * 32 + sigma) * 64 + c4);
            xphi[r * 65 + c4 + 0] = v.x; xphi[r * 65 + c4 + 1] = v.y;
            xphi[r * 65 + c4 + 2] = v.z; xphi[r * 65 + c4 + 3] = v.w;
        }
        Th[tid] = g_theta[((tg * 4 + (tid >> 6)) * 32 + sigma) * 64 + (tid & 63)];
        if (tid < 64)
            Td[tid] = g_thetaD[((tg * 4 + (tid >> 4)) * 32 + sigma) * 16 + (tid & 15)];

        float tp[10];
        {
            const float2* src = reinterpret_cast<const float2*>(
                temp + (((tau * 64 + t) * 32) + sigma) * 10);
            #pragma unroll
            for (int i = 0; i < 5; i++) { float2 v = src[i]; tp[2*i] = v.x; tp[2*i+1] = v.y; }
        }
        __syncthreads();

        float s = 0.f;
        #pragma unroll
        for (int a = 0; a < 64; a++) s += Th[tl * 64 + a] * xphi[t * 65 + a];
        #pragma unroll
        for (int d = 0; d < 10; d++) s += Td[tl * 16 + d] * tp[d];

        float m = s;
        #pragma unroll
        for (int o = 16; o; o >>= 1) m = fmaxf(m, __shfl_xor_sync(0xffffffffu, m, o));
        if (lane == 0) mxs[w] = m;
        __syncthreads();
        float M = fmaxf(mxs[tl], mxs[tl + 4]);
        float e = __expf(s - M);
        float psum = e;
        #pragma unroll
        for (int o = 16; o; o >>= 1) psum += __shfl_xor_sync(0xffffffffu, psum, o);
        if (lane == 0) sms[w] = psum;
        __syncthreads();
        float b = e / (sms[tl] + sms[tl + 4]);
        bsh[t * 4 + tl] = b;

        #pragma unroll
        for (int d = 0; d < 10; d++) {
            float v = b * tp[d];
            #pragma unroll
            for (int o = 16; o; o >>= 1) v += __shfl_xor_sync(0xffffffffu, v, o);
            if (lane == d) cdp[w * 10 + d] = v;
        }
        __syncthreads();
        if (tid < 40) cdc[tid] = cdp[tid] + cdp[tid + 40];
        __syncthreads();

        {
            int tl2 = tid >> 6, p = tid & 63;
            int q = (tg * 4 + tl2) * 32 + sigma;
            float v = btmp[p];
            #pragma unroll
            for (int d = 0; d < 10; d++) v += cdc[tl2 * 10 + d] * Wtmp[d * 64 + p];
            g_ctxp[q * 64 + p] = v;
        }

        __syncthreads();
        float* A = g_A4 + sigma * (64 * 64) + tg * 4;
        if (tid < 64) {
            *reinterpret_cast<float4*>(A + tid * 64) =
                *reinterpret_cast<const float4*>(bsh + tid * 4);
        }
        return;
    }

    // ---- spatial branch (inline posscore) ----
    float* xphi_s = sm;           // 32*65 = 2080
    float* xg_s   = sm + 2080;    // 32*256 = 8192
    float* Th     = sm + 10272;   // 8*64
    float* TB     = sm + 10784;   // 8*64
    float* asc    = sm + 11296;   // 8*33

    int b3 = blockIdx.x - 512;
    int tau = b3 >> 2;
    int sq = b3 & 3;              // sigmas [sq*8, sq*8+8)

    for (int e = tid; e < 512; e += 256) {
        int k = e >> 4, c4 = (e & 15) << 2;
        float4 v = *reinterpret_cast<const float4*>(g_xphi + (tau * 32 + k) * 64 + c4);
        xphi_s[k * 65 + c4 + 0] = v.x; xphi_s[k * 65 + c4 + 1] = v.y;
        xphi_s[k * 65 + c4 + 2] = v.z; xphi_s[k * 65 + c4 + 3] = v.w;
    }
    for (int e = tid; e < 2048; e += 256) {
        int k = e >> 6, c4 = (e & 63) << 2;
        float4 v = *reinterpret_cast<const float4*>(g_xg + (tau * 32 + k) * 256 + c4);
        *reinterpret_cast<float4*>(&xg_s[k * 256 + c4]) = v;
    }
    for (int e = tid; e < 512; e += 256) {
        int sig = e >> 6, c = e & 63;
        Th[sig * 64 + c] = g_theta[(tau * 32 + sq * 8 + sig) * 64 + c];
        TB[sig * 64 + c] = g_thetaB[(tau * 32 + sq * 8 + sig) * 64 + c];
    }
    __syncthreads();

    // scores (incl. inline posscore): warp w = sigma sq*8+w, lane = k
    {
        int sigma = sq * 8 + w;
        float s = 0.f;
        #pragma unroll
        for (int a = 0; a < 64; a++) s += Th[w * 64 + a] * xphi_s[lane * 65 + a];
        const float4* pp = reinterpret_cast<const float4*>(
            g_pos + sigma * 2048 + lane * 64);
        #pragma unroll
        for (int pg = 0; pg < 16; pg++) {
            float4 pv = pp[pg];
            s += TB[w * 64 + pg * 4 + 0] * pv.x + TB[w * 64 + pg * 4 + 1] * pv.y
               + TB[w * 64 + pg * 4 + 2] * pv.z + TB[w * 64 + pg * 4 + 3] * pv.w;
        }
        asc[w * 33 + lane] = s;
    }
    __syncwarp();

    // softmax (warp-local)
    {
        float s = asc[w * 33 + lane];
        float m = s;
        #pragma unroll
        for (int o = 16; o; o >>= 1) m = fmaxf(m, __shfl_xor_sync(0xffffffffu, m, o));
        float e = __expf(s - m);
        float sum = e;
        #pragma unroll
        for (int o = 16; o; o >>= 1) sum += __shfl_xor_sync(0xffffffffu, sum, o);
        asc[w * 33 + lane] = e / sum;
    }
    __syncwarp();

    // ctx: warp w owns sigma; lane covers 8 f's and 2 p's
    {
        int sigma = sq * 8 + w;
        int q = tau * 32 + sigma;
        float4 acc0 = {0,0,0,0}, acc1 = {0,0,0,0};
        float cp0 = 0.f, cp1 = 0.f;
        const float* posb = g_pos + sigma * (32 * 64);
        #pragma unroll 4
        for (int k = 0; k < 32; k++) {
            float aw = asc[w * 33 + k];
            const float* xr = &xg_s[k * 256 + lane * 8];
            float4 x0 = *reinterpret_cast<const float4*>(xr + 0);
            float4 x1 = *reinterpret_cast<const float4*>(xr + 4);
            acc0.x += aw*x0.x; acc0.y += aw*x0.y; acc0.z += aw*x0.z; acc0.w += aw*x0.w;
            acc1.x += aw*x1.x; acc1.y += aw*x1.y; acc1.z += aw*x1.z; acc1.w += aw*x1.w;
            float2 pv = *reinterpret_cast<const float2*>(posb + k * 64 + lane * 2);
            cp0 += aw * pv.x; cp1 += aw * pv.y;
        }
        float* og = g_ctxg + q * 256 + lane * 8;
        *reinterpret_cast<float4*>(og + 0) = acc0;
        *reinterpret_cast<float4*>(og + 4) = acc1;
        float2 cpv; cpv.x = cp0; cpv.y = cp1;
        *reinterpret_cast<float2*>(g_ctxp2 + q * 64 + lane * 2) = cpv;
    }
}

// ---------------------------------------------------------------------------
// L3: out[tau,f] = [attn | ctxp+ctxp2]^T(64x128) @ [xg ; WgP](128x64)
//                  + ctxg + 2bg.
// grid 512 = (sigma 32, fc 4, tau-quarter 4); 128 threads; tile 16tau x 64f,
// 2x4 micro-tile (A stride 20: float2/float4 aligned).
// ---------------------------------------------------------------------------
__global__ __launch_bounds__(128)
void k4b_out(const float* __restrict__ Wg,
             const float* __restrict__ bg,
             float* __restrict__ out) {
    __shared__ float As[64 * 20];   // [k][tau16], stride 20
    __shared__ float Bs[64 * 64];   // [k][f]
    int tid = threadIdx.x;
    int b = blockIdx.x;
    int sigma = b & 31;
    int fc = (b >> 5) & 3;
    int tq = b >> 7;                // tau quarter: taus [tq*16, tq*16+16)
    int f0 = fc * 64;

    const int tcol = tid & 15, trow = tid >> 4;   // trow 0..7 -> 2 taus each
    float acc[2][4] = {};

    #pragma unroll
    for (int kc = 0; kc < 2; kc++) {
        if (kc == 0) {
            const float* Ag = g_A4 + sigma * (64 * 64) + tq * 16;
            #pragma unroll
            for (int li = 0; li < 2; li++) {      // 64k x 16tau = 256 float4
                int e = tid + li * 128;
                int k = e >> 2, c4 = (e & 3) << 2;
                float4 v = *reinterpret_cast<const float4*>(Ag + k * 64 + c4);
                *reinterpret_cast<float4*>(&As[k * 20 + c4]) = v;
            }
            #pragma unroll
            for (int li = 0; li < 8; li++) {      // B: 64x64 = 1024 float4
                int e = tid + li * 128;
                int r = e >> 4, c4 = (e & 15) << 2;
                float4 v = *reinterpret_cast<const float4*>(
                    g_xg + (r * 32 + sigma) * 256 + f0 + c4);
                *reinterpret_cast<float4*>(&Bs[r * 64 + c4]) = v;
            }
        } else {
            // A = transpose of (g_ctxp + g_ctxp2) tile (16 tau x 64 p)
            #pragma unroll
            for (int li = 0; li < 2; li++) {
                int e = tid + li * 128;
                int tl = e >> 4, pg = e & 15;
                int q = (tq * 16 + tl) * 32 + sigma;
                float4 v = *reinterpret_cast<const float4*>(g_ctxp + q * 64 + pg * 4);
                float4 u = *reinterpret_cast<const float4*>(g_ctxp2 + q * 64 + pg * 4);
                As[(pg * 4 + 0) * 20 + tl] = v.x + u.x;
                As[(pg * 4 + 1) * 20 + tl] = v.y + u.y;
                As[(pg * 4 + 2) * 20 + tl] = v.z + u.z;
                As[(pg * 4 + 3) * 20 + tl] = v.w + u.w;
            }
            #pragma unroll
            for (int li = 0; li < 8; li++) {
                int e = tid + li * 128;
                int r = e >> 4, c4 = (e & 15) << 2;
                float4 v = *reinterpret_cast<const float4*>(
                    Wg + (256 + r) * 256 + f0 + c4);
                *reinterpret_cast<float4*>(&Bs[r * 64 + c4]) = v;
            }
        }
        __syncthreads();
        #pragma unroll 8
        for (int k = 0; k < 64; k++) {
            float2 av = *reinterpret_cast<const float2*>(&As[k * 20 + trow * 2]);
            float4 bv = *reinterpret_cast<const float4*>(&Bs[k * 64 + tcol * 4]);
            acc[0][0] += av.x * bv.x; acc[0][1] += av.x * bv.y;
            acc[0][2] += av.x * bv.z; acc[0][3] += av.x * bv.w;
            acc[1][0] += av.y * bv.x; acc[1][1] += av.y * bv.y;
            acc[1][2] += av.y * bv.z; acc[1][3] += av.y * bv.w;
        }
        __syncthreads();
    }

    float4 bgv = *reinterpret_cast<const float4*>(bg + f0 + tcol * 4);
    #pragma unroll
    for (int i = 0; i < 2; i++) {
        int tau = tq * 16 + trow * 2 + i;
        int o = (tau * 32 + sigma) * 256 + f0 + tcol * 4;
        float4 cg = *reinterpret_cast<const float4*>(g_ctxg + o);
        float4 r;
        r.x = acc[i][0] + cg.x + 2.f * bgv.x;
        r.y = acc[i][1] + cg.y + 2.f * bgv.y;
        r.z = acc[i][2] + cg.z + 2.f * bgv.z;
        r.w = acc[i][3] + cg.w + 2.f * bgv.w;
        *reinterpret_cast<float4*>(out + o) = r;
    }
}

// ---------------------------------------------------------------------------
extern "C" void kernel_launch(void* const* d_in, const int* in_sizes, int n_in,
                              void* d_out, int out_size) {
    (void)in_sizes; (void)n_in; (void)out_size;
    const float* batch_data = (const float*)d_in[0];
    const float* positions  = (const float*)d_in[1];
    const float* temp       = (const float*)d_in[2];
    const float* Wa         = (const float*)d_in[3];
    const float* ba         = (const float*)d_in[4];
    const float* Wb         = (const float*)d_in[5];
    // d_in[6] = bb : cancels in softmax -> unused
    const float* Wg         = (const float*)d_in[7];
    const float* bg         = (const float*)d_in[8];
    const float* Wpos       = (const float*)d_in[9];
    const float* bpos       = (const float*)d_in[10];
    const float* Wtmp       = (const float*)d_in[11];
    const float* btmp       = (const float*)d_in[12];
    float* out = (float*)d_out;

    k1_proj<<<dim3(64, 7), 128>>>(batch_data, Wa, Wb, Wg, ba, Wtmp,
                                  positions, Wpos, bpos);
    kbig<<<768, 256>>>(temp, Wtmp, btmp);
    k4b_out<<<512, 128>>>(Wg, bg, out);
}

// round 14
// speedup vs baseline: 1.2615x; 1.1084x over previous
#include <cuda_runtime.h>
#include <cuda_bf16.h>

// Problem constants
#define T_ 64
#define S_ 32
#define F_ 256
#define A_ 64
#define P2_ 64   // 2*P
#define NQ_ 2048 // T*S

// Scratch (device globals; no allocations allowed)
__device__ float g_theta[NQ_ * A_];
__device__ float g_xphi[NQ_ * A_];
__device__ float g_xg[NQ_ * F_];
__device__ float g_thetaB[NQ_ * P2_];
__device__ float g_thetaD[NQ_ * 16];      // 10 used, padded
__device__ float g_pos[S_ * S_ * P2_];    // pos[sigma][k][p]
__device__ float g_ctxg[NQ_ * F_];        // spatial ctx_g
__device__ float g_ctxp[NQ_ * P2_];       // temporal: btmp + cd@Wtmp
__device__ float g_ctxp2[NQ_ * P2_];      // spatial ctx_p (separate: no race)
// g_A4[sigma][t][tau] : temporal attention matrix (K-major operand for k4b)
__device__ float g_A4[S_ * T_ * T_];

// k1 dynamic smem: Xs 32x132 + Ws 128x68
#define K1_XS 4224
#define K1_WS 8704
#define K1_SMEMF (K1_XS + K1_WS)
#define K1_SMEMB (K1_SMEMF * 4)   // 51712 bytes

// ---------------------------------------------------------------------------
// L1: seg 0..5 = projection GEMM x @ [Wa | WbX | WgX] (+thetaB/thetaD on seg0)
//     seg 6    = pos embedding (independent work, same launch)
// grid (64, 7), 128 threads. 32M x 64N tiles, 4x4 micro-tile,
// K-chunks of 128 (2 chunks -> 4 barriers/block).
// ---------------------------------------------------------------------------
__global__ __launch_bounds__(128)
void k1_proj(const float* __restrict__ x,
             const float* __restrict__ Wa,
             const float* __restrict__ Wb,
             const float* __restrict__ Wg,
             const float* __restrict__ ba,
             const float* __restrict__ Wtmp,
             const float* __restrict__ positions,
             const float* __restrict__ Wpos,
             const float* __restrict__ bpos) {
    extern __shared__ float dsm[];
    float* Xs = dsm;             // [32][132]
    float* Ws = dsm + K1_XS;     // [128][68]
    const int tid = threadIdx.x;
    const int m0 = blockIdx.x * 32;
    const int seg = blockIdx.y;

    if (seg == 6) {
        int base = blockIdx.x * 1024;
        #pragma unroll
        for (int li = 0; li < 8; li++) {
            int idx = base + tid + li * 128;
            int p = idx & 63;
            int jk = idx >> 6;
            int half = p >> 5, pp = p & 31;
            const float* src = positions + half * (S_*S_*9) + jk * 9;
            float s = bpos[pp];
            #pragma unroll
            for (int d = 0; d < 9; d++) s += src[d] * Wpos[d * 32 + pp];
            g_pos[idx] = s;
        }
        return;
    }

    const float* W;
    float* out;
    int ldw, coloff, ldo;
    bool addb = false;
    if (seg == 0)      { W = Wa; ldw = 64;  coloff = 0;          out = g_theta; ldo = 64;  addb = true; }
    else if (seg == 1) { W = Wb; ldw = 64;  coloff = 0;          out = g_xphi;  ldo = 64; }
    else               { W = Wg; ldw = 256; coloff = (seg-2)*64; out = g_xg;    ldo = 256; }

    const int tcol = tid & 15, trow = tid >> 4;   // trow 0..7 -> 4 rows each
    float acc[4][4] = {};

    #pragma unroll
    for (int kc = 0; kc < 2; kc++) {
        int kk = kc * 128;
        #pragma unroll
        for (int li = 0; li < 8; li++) {          // X: 32x128 = 1024 float4
            int f = tid + li * 128;
            int r = f >> 5, c4 = (f & 31) << 2;
            float4 v = *reinterpret_cast<const float4*>(x + (m0 + r) * 256 + kk + c4);
            Xs[r * 132 + c4 + 0] = v.x; Xs[r * 132 + c4 + 1] = v.y;
            Xs[r * 132 + c4 + 2] = v.z; Xs[r * 132 + c4 + 3] = v.w;
        }
        #pragma unroll
        for (int li = 0; li < 16; li++) {         // W: 128x64 = 2048 float4
            int f = tid + li * 128;
            int r = f >> 4, c4 = (f & 15) << 2;
            float4 v = *reinterpret_cast<const float4*>(W + (kk + r) * ldw + coloff + c4);
            *reinterpret_cast<float4*>(&Ws[r * 68 + c4]) = v;
        }
        __syncthreads();
        #pragma unroll 16
        for (int k = 0; k < 128; k++) {
            float a[4];
            #pragma unroll
            for (int i = 0; i < 4; i++) a[i] = Xs[(trow*4 + i) * 132 + k];
            float4 bv = *reinterpret_cast<const float4*>(&Ws[k * 68 + tcol*4]);
            float b[4] = {bv.x, bv.y, bv.z, bv.w};
            #pragma unroll
            for (int i = 0; i < 4; i++)
                #pragma unroll
                for (int j = 0; j < 4; j++) acc[i][j] += a[i] * b[j];
        }
        __syncthreads();
    }
    #pragma unroll
    for (int i = 0; i < 4; i++) {
        int r = trow*4 + i;
        #pragma unroll
        for (int j = 0; j < 4; j++) {
            int c = tcol*4 + j;
            float v = acc[i][j];
            if (addb) v += ba[c];
            out[(m0 + r) * ldo + coloff + c] = v;
            if (seg == 0) Xs[r * 132 + c] = v;
        }
    }
    if (seg != 0) return;

    // --- thetaB = theta @ WbP^T : WbP laid out as Ws[a][p] ---
    __syncthreads();
    #pragma unroll
    for (int li = 0; li < 32; li++) {
        int e = tid + li * 128;            // e = p*64 + a
        int p = e >> 6, a = e & 63;
        Ws[a * 68 + p] = Wb[(256 + p) * 64 + a];
    }
    __syncthreads();
    float acc2[4][4] = {};
    #pragma unroll 16
    for (int a = 0; a < 64; a++) {
        float av[4];
        #pragma unroll
        for (int i = 0; i < 4; i++) av[i] = Xs[(trow*4 + i) * 132 + a];
        float4 bv = *reinterpret_cast<const float4*>(&Ws[a * 68 + tcol*4]);
        float b[4] = {bv.x, bv.y, bv.z, bv.w};
        #pragma unroll
        for (int i = 0; i < 4; i++)
            #pragma unroll
            for (int j = 0; j < 4; j++) acc2[i][j] += av[i] * b[j];
    }
    __syncthreads();
    #pragma unroll
    for (int i = 0; i < 4; i++) {
        int r = trow*4 + i;
        #pragma unroll
        for (int j = 0; j < 4; j++) {
            int p = tcol*4 + j;
            g_thetaB[(m0 + r) * 64 + p] = acc2[i][j];
            Xs[r * 132 + p] = acc2[i][j];
        }
    }
    __syncthreads();
    for (int e = tid; e < 320; e += 128) {
        int r = e / 10, d = e % 10;
        float s = 0.f;
        #pragma unroll
        for (int p = 0; p < 64; p++) s += Xs[r * 132 + p] * Wtmp[d * 64 + p];
        g_thetaD[(m0 + r) * 16 + d] = s;
    }
}

// ---------------------------------------------------------------------------
// L2: kbig. blocks 0..255 = temporal scores (writes g_A4, g_ctxp);
//          blocks 256..511 = spatial attention with inline posscore
//          (writes g_ctxg, g_ctxp2). Both depend only on L1.
// Temporal: warp <-> tau (8 per block), lane <-> t-pair; xphiT [a][t] layout
// gives 2 FMA per 2 LDS and a fully warp-local softmax.
// ---------------------------------------------------------------------------
__global__ __launch_bounds__(256)
void kbig(const float* __restrict__ temp,
          const float* __restrict__ Wtmp,
          const float* __restrict__ btmp) {
    __shared__ float sm[11560];
    int tid = threadIdx.x, lane = tid & 31, w = tid >> 5;

    if (blockIdx.x < 256) {
        // ---- temporal branch ----
        float* xphiT = sm;            // [a][t] 64*66 = 4224
        float* Th    = sm + 4224;     // 8*64
        float* Td    = sm + 4736;     // 8*16
        float* bsh   = sm + 4864;     // [t][tl] 64*8
        float* Wts   = sm + 5376;     // 640

        int sigma = blockIdx.x & 31;
        int tg8 = blockIdx.x >> 5;         // taus [tg8*8, tg8*8+8)
        int tau = tg8 * 8 + w;
        int t0 = lane * 2, t1 = t0 + 1;

        // stage xphiT (transpose), Th, Td, Wtmp
        for (int e = tid; e < 1024; e += 256) {
            int t = e >> 4, c4 = (e & 15) << 2;
            float4 v = *reinterpret_cast<const float4*>(g_xphi + (t * 32 + sigma) * 64 + c4);
            xphiT[(c4 + 0) * 66 + t] = v.x;
            xphiT[(c4 + 1) * 66 + t] = v.y;
            xphiT[(c4 + 2) * 66 + t] = v.z;
            xphiT[(c4 + 3) * 66 + t] = v.w;
        }
        for (int e = tid; e < 512; e += 256) {
            int tl = e >> 6, a = e & 63;
            Th[e] = g_theta[((tg8 * 8 + tl) * 32 + sigma) * 64 + a];
        }
        if (tid < 128) {
            int tl = tid >> 4;
            Td[tid] = g_thetaD[((tg8 * 8 + tl) * 32 + sigma) * 16 + (tid & 15)];
        }
        for (int e = tid; e < 640; e += 256) Wts[e] = Wtmp[e];

        // temp in registers
        float tp0[10], tp1[10];
        {
            const float2* s0p = reinterpret_cast<const float2*>(
                temp + (((tau * 64 + t0) * 32) + sigma) * 10);
            const float2* s1p = reinterpret_cast<const float2*>(
                temp + (((tau * 64 + t1) * 32) + sigma) * 10);
            #pragma unroll
            for (int i = 0; i < 5; i++) {
                float2 v0 = s0p[i]; tp0[2*i] = v0.x; tp0[2*i+1] = v0.y;
                float2 v1 = s1p[i]; tp1[2*i] = v1.x; tp1[2*i+1] = v1.y;
            }
        }
        __syncthreads();

        // scores
        float s0 = 0.f, s1 = 0.f;
        #pragma unroll 16
        for (int a = 0; a < 64; a++) {
            float th = Th[w * 64 + a];
            float2 xv = *reinterpret_cast<const float2*>(&xphiT[a * 66 + t0]);
            s0 += th * xv.x;
            s1 += th * xv.y;
        }
        #pragma unroll
        for (int d = 0; d < 10; d++) {
            float td = Td[w * 16 + d];
            s0 += td * tp0[d];
            s1 += td * tp1[d];
        }

        // warp-local softmax over 64 t's
        float m = fmaxf(s0, s1);
        #pragma unroll
        for (int o = 16; o; o >>= 1) m = fmaxf(m, __shfl_xor_sync(0xffffffffu, m, o));
        float e0 = __expf(s0 - m), e1 = __expf(s1 - m);
        float sum = e0 + e1;
        #pragma unroll
        for (int o = 16; o; o >>= 1) sum += __shfl_xor_sync(0xffffffffu, sum, o);
        float inv = 1.f / sum;
        float b0 = e0 * inv, b1 = e1 * inv;
        bsh[t0 * 8 + w] = b0;
        bsh[t1 * 8 + w] = b1;

        // cd in registers (warp-uniform after reduction)
        float cdv[10];
        #pragma unroll
        for (int d = 0; d < 10; d++) {
            float v = b0 * tp0[d] + b1 * tp1[d];
            #pragma unroll
            for (int o = 16; o; o >>= 1) v += __shfl_xor_sync(0xffffffffu, v, o);
            cdv[d] = v;
        }

        // cps -> g_ctxp (coalesced; warp-local)
        {
            int q = tau * 32 + sigma;
            int p0 = lane, p1 = lane + 32;
            float v0 = btmp[p0], v1 = btmp[p1];
            #pragma unroll
            for (int d = 0; d < 10; d++) {
                v0 += cdv[d] * Wts[d * 64 + p0];
                v1 += cdv[d] * Wts[d * 64 + p1];
            }
            g_ctxp[q * 64 + p0] = v0;
            g_ctxp[q * 64 + p1] = v1;
        }

        __syncthreads();
        // attn -> g_A4[sigma][t][tau]: 512 floats, 1 float2 per thread
        {
            int t = tid >> 2, tlp = (tid & 3) * 2;
            float2 bv = *reinterpret_cast<const float2*>(&bsh[t * 8 + tlp]);
            *reinterpret_cast<float2*>(
                g_A4 + sigma * 4096 + t * 64 + tg8 * 8 + tlp) = bv;
        }
        return;
    }

    // ---- spatial branch (inline posscore) ----
    float* xphi_s = sm;           // 32*65 = 2080
    float* xg_s   = sm + 2080;    // 32*256 = 8192
    float* Th     = sm + 10272;   // 8*64
    float* TB     = sm + 10784;   // 8*64
    float* asc    = sm + 11296;   // 8*33

    int b3 = blockIdx.x - 256;
    int tau = b3 >> 2;
    int sq = b3 & 3;              // sigmas [sq*8, sq*8+8)

    for (int e = tid; e < 512; e += 256) {
        int k = e >> 4, c4 = (e & 15) << 2;
        float4 v = *reinterpret_cast<const float4*>(g_xphi + (tau * 32 + k) * 64 + c4);
        xphi_s[k * 65 + c4 + 0] = v.x; xphi_s[k * 65 + c4 + 1] = v.y;
        xphi_s[k * 65 + c4 + 2] = v.z; xphi_s[k * 65 + c4 + 3] = v.w;
    }
    for (int e = tid; e < 2048; e += 256) {
        int k = e >> 6, c4 = (e & 63) << 2;
        float4 v = *reinterpret_cast<const float4*>(g_xg + (tau * 32 + k) * 256 + c4);
        *reinterpret_cast<float4*>(&xg_s[k * 256 + c4]) = v;
    }
    for (int e = tid; e < 512; e += 256) {
        int sig = e >> 6, c = e & 63;
        Th[sig * 64 + c] = g_theta[(tau * 32 + sq * 8 + sig) * 64 + c];
        TB[sig * 64 + c] = g_thetaB[(tau * 32 + sq * 8 + sig) * 64 + c];
    }
    __syncthreads();

    // scores (incl. inline posscore): warp w = sigma sq*8+w, lane = k
    {
        int sigma = sq * 8 + w;
        float s = 0.f;
        #pragma unroll
        for (int a = 0; a < 64; a++) s += Th[w * 64 + a] * xphi_s[lane * 65 + a];
        const float4* pp = reinterpret_cast<const float4*>(
            g_pos + sigma * 2048 + lane * 64);
        #pragma unroll
        for (int pg = 0; pg < 16; pg++) {
            float4 pv = pp[pg];
            s += TB[w * 64 + pg * 4 + 0] * pv.x + TB[w * 64 + pg * 4 + 1] * pv.y
               + TB[w * 64 + pg * 4 + 2] * pv.z + TB[w * 64 + pg * 4 + 3] * pv.w;
        }
        asc[w * 33 + lane] = s;
    }
    __syncwarp();

    // softmax (warp-local)
    {
        float s = asc[w * 33 + lane];
        float m = s;
        #pragma unroll
        for (int o = 16; o; o >>= 1) m = fmaxf(m, __shfl_xor_sync(0xffffffffu, m, o));
        float e = __expf(s - m);
        float sum = e;
        #pragma unroll
        for (int o = 16; o; o >>= 1) sum += __shfl_xor_sync(0xffffffffu, sum, o);
        asc[w * 33 + lane] = e / sum;
    }
    __syncwarp();

    // ctx: warp w owns sigma; lane covers 8 f's and 2 p's
    {
        int sigma = sq * 8 + w;
        int q = tau * 32 + sigma;
        float4 acc0 = {0,0,0,0}, acc1 = {0,0,0,0};
        float cp0 = 0.f, cp1 = 0.f;
        const float* posb = g_pos + sigma * (32 * 64);
        #pragma unroll 4
        for (int k = 0; k < 32; k++) {
            float aw = asc[w * 33 + k];
            const float* xr = &xg_s[k * 256 + lane * 8];
            float4 x0 = *reinterpret_cast<const float4*>(xr + 0);
            float4 x1 = *reinterpret_cast<const float4*>(xr + 4);
            acc0.x += aw*x0.x; acc0.y += aw*x0.y; acc0.z += aw*x0.z; acc0.w += aw*x0.w;
            acc1.x += aw*x1.x; acc1.y += aw*x1.y; acc1.z += aw*x1.z; acc1.w += aw*x1.w;
            float2 pv = *reinterpret_cast<const float2*>(posb + k * 64 + lane * 2);
            cp0 += aw * pv.x; cp1 += aw * pv.y;
        }
        float* og = g_ctxg + q * 256 + lane * 8;
        *reinterpret_cast<float4*>(og + 0) = acc0;
        *reinterpret_cast<float4*>(og + 4) = acc1;
        float2 cpv; cpv.x = cp0; cpv.y = cp1;
        *reinterpret_cast<float2*>(g_ctxp2 + q * 64 + lane * 2) = cpv;
    }
}

// ---------------------------------------------------------------------------
// L3: out[tau,f] = [attn | ctxp+ctxp2]^T(64x128) @ [xg ; WgP](128x64)
//                  + ctxg + 2bg.
// grid 512 = (sigma 32, fc 4, tau-quarter 4); 128 threads; tile 16tau x 64f,
// 2x4 micro-tile (A stride 20).
// ---------------------------------------------------------------------------
__global__ __launch_bounds__(128)
void k4b_out(const float* __restrict__ Wg,
             const float* __restrict__ bg,
             float* __restrict__ out) {
    __shared__ float As[64 * 20];   // [k][tau16], stride 20
    __shared__ float Bs[64 * 64];   // [k][f]
    int tid = threadIdx.x;
    int b = blockIdx.x;
    int sigma = b & 31;
    int fc = (b >> 5) & 3;
    int tq = b >> 7;                // tau quarter: taus [tq*16, tq*16+16)
    int f0 = fc * 64;

    const int tcol = tid & 15, trow = tid >> 4;   // trow 0..7 -> 2 taus each
    float acc[2][4] = {};

    #pragma unroll
    for (int kc = 0; kc < 2; kc++) {
        if (kc == 0) {
            const float* Ag = g_A4 + sigma * (64 * 64) + tq * 16;
            #pragma unroll
            for (int li = 0; li < 2; li++) {
                int e = tid + li * 128;
                int k = e >> 2, c4 = (e & 3) << 2;
                float4 v = *reinterpret_cast<const float4*>(Ag + k * 64 + c4);
                *reinterpret_cast<float4*>(&As[k * 20 + c4]) = v;
            }
            #pragma unroll
            for (int li = 0; li < 8; li++) {
                int e = tid + li * 128;
                int r = e >> 4, c4 = (e & 15) << 2;
                float4 v = *reinterpret_cast<const float4*>(
                    g_xg + (r * 32 + sigma) * 256 + f0 + c4);
                *reinterpret_cast<float4*>(&Bs[r * 64 + c4]) = v;
            }
        } else {
            #pragma unroll
            for (int li = 0; li < 2; li++) {
                int e = tid + li * 128;
                int tl = e >> 4, pg = e & 15;
                int q = (tq * 16 + tl) * 32 + sigma;
                float4 v = *reinterpret_cast<const float4*>(g_ctxp + q * 64 + pg * 4);
                float4 u = *reinterpret_cast<const float4*>(g_ctxp2 + q * 64 + pg * 4);
                As[(pg * 4 + 0) * 20 + tl] = v.x + u.x;
                As[(pg * 4 + 1) * 20 + tl] = v.y + u.y;
                As[(pg * 4 + 2) * 20 + tl] = v.z + u.z;
                As[(pg * 4 + 3) * 20 + tl] = v.w + u.w;
            }
            #pragma unroll
            for (int li = 0; li < 8; li++) {
                int e = tid + li * 128;
                int r = e >> 4, c4 = (e & 15) << 2;
                float4 v = *reinterpret_cast<const float4*>(
                    Wg + (256 + r) * 256 + f0 + c4);
                *reinterpret_cast<float4*>(&Bs[r * 64 + c4]) = v;
            }
        }
        __syncthreads();
        #pragma unroll 8
        for (int k = 0; k < 64; k++) {
            float2 av = *reinterpret_cast<const float2*>(&As[k * 20 + trow * 2]);
            float4 bv = *reinterpret_cast<const float4*>(&Bs[k * 64 + tcol * 4]);
            acc[0][0] += av.x * bv.x; acc[0][1] += av.x * bv.y;
            acc[0][2] += av.x * bv.z; acc[0][3] += av.x * bv.w;
            acc[1][0] += av.y * bv.x; acc[1][1] += av.y * bv.y;
            acc[1][2] += av.y * bv.z; acc[1][3] += av.y * bv.w;
        }
        __syncthreads();
    }

    float4 bgv = *reinterpret_cast<const float4*>(bg + f0 + tcol * 4);
    #pragma unroll
    for (int i = 0; i < 2; i++) {
        int tau = tq * 16 + trow * 2 + i;
        int o = (tau * 32 + sigma) * 256 + f0 + tcol * 4;
        float4 cg = *reinterpret_cast<const float4*>(g_ctxg + o);
        float4 r;
        r.x = acc[i][0] + cg.x + 2.f * bgv.x;
        r.y = acc[i][1] + cg.y + 2.f * bgv.y;
        r.z = acc[i][2] + cg.z + 2.f * bgv.z;
        r.w = acc[i][3] + cg.w + 2.f * bgv.w;
        *reinterpret_cast<float4*>(out + o) = r;
    }
}

// ---------------------------------------------------------------------------
extern "C" void kernel_launch(void* const* d_in, const int* in_sizes, int n_in,
                              void* d_out, int out_size) {
    (void)in_sizes; (void)n_in; (void)out_size;
    const float* batch_data = (const float*)d_in[0];
    const float* positions  = (const float*)d_in[1];
    const float* temp       = (const float*)d_in[2];
    const float* Wa         = (const float*)d_in[3];
    const float* ba         = (const float*)d_in[4];
    const float* Wb         = (const float*)d_in[5];
    // d_in[6] = bb : cancels in softmax -> unused
    const float* Wg         = (const float*)d_in[7];
    const float* bg         = (const float*)d_in[8];
    const float* Wpos       = (const float*)d_in[9];
    const float* bpos       = (const float*)d_in[10];
    const float* Wtmp       = (const float*)d_in[11];
    const float* btmp       = (const float*)d_in[12];
    float* out = (float*)d_out;

    cudaFuncSetAttribute((const void*)k1_proj,
                         cudaFuncAttributeMaxDynamicSharedMemorySize, K1_SMEMB);

    k1_proj<<<dim3(64, 7), 128, K1_SMEMB>>>(batch_data, Wa, Wb, Wg, ba, Wtmp,
                                            positions, Wpos, bpos);
    kbig<<<512, 256>>>(temp, Wtmp, btmp);
    k4b_out<<<512, 128>>>(Wg, bg, out);
}